// round 4
// baseline (speedup 1.0000x reference)
#include <cuda_runtime.h>

// InteractiveGallingModelV6: 150-step stochastic recurrence, 65536 lanes.
// One thread per batch lane; sequential loop over the 150 cycles with
// one-iteration-ahead prefetch of (u, noise). All math via MUFU intrinsics.
//
// Inputs (metadata order): params[17] f32, T scalar f32, u [150,65536] f32,
// noise [150,65536] f32. Output [7,150,65536] f32:
//   plane 0: mu_next, 1: component, 2: pi, 3: d1, 4: sigma1, 5: d2, 6: sigma2

#define N_CYCLES 150
#define BATCH    65536
#define T_REF    160.0f
#define MU_MIN   0.1f
#define MU_MAX   1.3f

__device__ __forceinline__ float fast_sigmoid(float x) {
    // 1 / (1 + exp(-x)) : MUFU.EX2 + MUFU.RCP
    float e = __expf(-x);
    return __fdividef(1.0f, 1.0f + e);
}

__device__ __forceinline__ float fast_softplus(float x) {
    // numerically safe: max(x,0) + log1p(exp(-|x|)) : MUFU.EX2 + MUFU.LG2
    float ax = fabsf(x);
    float e  = __expf(-ax);
    return fmaxf(x, 0.0f) + __logf(1.0f + e);
}

__global__ void __launch_bounds__(256)
galling_v6_kernel(const float* __restrict__ params,
                  const float* __restrict__ Tptr,
                  const float* __restrict__ u,
                  const float* __restrict__ noise,
                  float* __restrict__ out)
{
    const int b = blockIdx.x * blockDim.x + threadIdx.x;

    // ---- parameters (L1/L2-broadcast loads, negligible) ----
    const float a0       = __ldg(params + 0);
    const float a_T      = __ldg(params + 1);
    const float a_mu     = __ldg(params + 2);
    const float a_mu2    = __ldg(params + 3);
    const float c0       = __ldg(params + 4);
    const float c_mu     = __ldg(params + 5);
    const float c_T      = __ldg(params + 6);
    const float s0       = __ldg(params + 7);
    const float s_mu     = __ldg(params + 8);
    const float s_T      = __ldg(params + 9);
    const float j0       = __ldg(params + 10);
    const float j_mu     = __ldg(params + 11);
    const float j_T      = __ldg(params + 12);
    const float v0       = __ldg(params + 13);
    const float v_mu     = __ldg(params + 14);
    const float mu0_base = __ldg(params + 15);
    const float mu0_T    = __ldg(params + 16);

    const float dT = __ldg(Tptr) - T_REF;

    // fold temperature terms into per-thread constants
    const float A = a0 + a_T * dT;   // pi arg   = A + a_mu*mu + a_mu2*mu^2
    const float C = c0 + c_T * dT;   // d1       = C + c_mu*mu
    const float S = s0 + s_T * dT;   // sigma1   = softplus(S + s_mu*mu)
    const float J = j0 + j_T * dT;   // d2       = J + j_mu*mu
    // sigma2 = softplus(v0 + v_mu*mu)

    float mu = fminf(fmaxf(mu0_base + mu0_T * dT, MU_MIN), MU_MAX);

    const float* __restrict__ up = u + b;
    const float* __restrict__ np = noise + b;

    const long long NB = (long long)N_CYCLES * BATCH;
    float* __restrict__ o0 = out + b;               // mu
    float* __restrict__ o1 = o0 + NB;               // component
    float* __restrict__ o2 = o1 + NB;               // pi
    float* __restrict__ o3 = o2 + NB;               // d1
    float* __restrict__ o4 = o3 + NB;               // sigma1
    float* __restrict__ o5 = o4 + NB;               // d2
    float* __restrict__ o6 = o5 + NB;               // sigma2

    // prefetch iteration 0
    float uc = __ldg(up);
    float nc = __ldg(np);

    #pragma unroll 2
    for (int t = 0; t < N_CYCLES; ++t) {
        // prefetch next iteration's inputs (hide DRAM latency behind compute+BW)
        float un = 0.0f, nn = 0.0f;
        if (t + 1 < N_CYCLES) {
            un = __ldg(up + (long long)(t + 1) * BATCH);
            nn = __ldg(np + (long long)(t + 1) * BATCH);
        }

        // per-step coefficients (functions of mu only)
        const float x_pi   = fmaf(mu, fmaf(mu, a_mu2, a_mu), A);
        const float pi     = fast_sigmoid(x_pi);
        const float d1     = fmaf(mu, c_mu, C);
        const float sigma1 = fast_softplus(fmaf(mu, s_mu, S));
        const float d2     = fmaf(mu, j_mu, J);
        const float sigma2 = fast_softplus(fmaf(mu, v_mu, v0));

        const bool  is_stay   = uc < pi;
        const float component = is_stay ? 0.0f : 1.0f;
        const float delta_mu  = is_stay ? fmaf(sigma1, nc, d1)
                                        : fmaf(sigma2, nc, d2);
        const float mu_next   = fminf(fmaxf(mu + delta_mu, MU_MIN), MU_MAX);

        const long long idx = (long long)t * BATCH;
        o0[idx] = mu_next;
        o1[idx] = component;
        o2[idx] = pi;
        o3[idx] = d1;
        o4[idx] = sigma1;
        o5[idx] = d2;
        o6[idx] = sigma2;

        mu = mu_next;
        uc = un;
        nc = nn;
    }
}

extern "C" void kernel_launch(void* const* d_in, const int* in_sizes, int n_in,
                              void* d_out, int out_size)
{
    const float* params = (const float*)d_in[0];
    const float* T      = (const float*)d_in[1];
    const float* u      = (const float*)d_in[2];
    const float* noise  = (const float*)d_in[3];
    float* out          = (float*)d_out;

    const int threads = 256;
    const int blocks  = BATCH / threads;  // 65536 / 256 = 256 blocks
    galling_v6_kernel<<<blocks, threads>>>(params, T, u, noise, out);
}

// round 7
// speedup vs baseline: 1.1589x; 1.1589x over previous
#include <cuda_runtime.h>

// InteractiveGallingModelV6: 150-step stochastic recurrence over 65536 lanes.
// v2 (resubmit after infra failure): 2 lanes per thread (float2 I/O),
// prefetch depth 2, streaming ld/st hints.
// Rationale: R1 kernel was latency/MLP-bound (dram 40%, issue 31%, occ 21%);
// doubling per-warp memory-level parallelism and halving ld/st instruction
// count pushes toward the HBM roofline.

#define N_CYCLES 150
#define BATCH    65536
#define HALF     (BATCH / 2)          // float2 elements per time step
#define T_REF    160.0f
#define MU_MIN   0.1f
#define MU_MAX   1.3f

struct Coef {
    float A, a_mu, a_mu2;   // pi arg    = A + a_mu*mu + a_mu2*mu^2
    float C, c_mu;          // d1        = C + c_mu*mu
    float S, s_mu;          // sigma1    = softplus(S + s_mu*mu)
    float J, j_mu;          // d2        = J + j_mu*mu
    float v0, v_mu;         // sigma2    = softplus(v0 + v_mu*mu)
};

__device__ __forceinline__ float fast_sigmoid(float x) {
    return __fdividef(1.0f, 1.0f + __expf(-x));      // MUFU.EX2 + MUFU.RCP
}
__device__ __forceinline__ float fast_softplus(float x) {
    // max(x,0) + log1p(exp(-|x|)) : MUFU.EX2 + MUFU.LG2, numerically safe
    return fmaxf(x, 0.0f) + __logf(1.0f + __expf(-fabsf(x)));
}

__device__ __forceinline__ void step_lane(const Coef& k, float& mu,
                                          float uc, float nc,
                                          float& pi, float& d1, float& s1,
                                          float& d2, float& s2, float& comp)
{
    const float x_pi = fmaf(mu, fmaf(mu, k.a_mu2, k.a_mu), k.A);
    pi = fast_sigmoid(x_pi);
    d1 = fmaf(mu, k.c_mu, k.C);
    s1 = fast_softplus(fmaf(mu, k.s_mu, k.S));
    d2 = fmaf(mu, k.j_mu, k.J);
    s2 = fast_softplus(fmaf(mu, k.v_mu, k.v0));

    const bool stay = uc < pi;
    comp = stay ? 0.0f : 1.0f;
    const float dmu = stay ? fmaf(s1, nc, d1) : fmaf(s2, nc, d2);
    mu = fminf(fmaxf(mu + dmu, MU_MIN), MU_MAX);
}

__global__ void __launch_bounds__(128)
galling_v6_kernel(const float* __restrict__ params,
                  const float* __restrict__ Tptr,
                  const float* __restrict__ u,
                  const float* __restrict__ noise,
                  float* __restrict__ out)
{
    const int b = blockIdx.x * blockDim.x + threadIdx.x;   // float2 lane index

    const float a0       = __ldg(params + 0);
    const float a_T      = __ldg(params + 1);
    const float a_mu     = __ldg(params + 2);
    const float a_mu2    = __ldg(params + 3);
    const float c0       = __ldg(params + 4);
    const float c_mu     = __ldg(params + 5);
    const float c_T      = __ldg(params + 6);
    const float s0       = __ldg(params + 7);
    const float s_mu     = __ldg(params + 8);
    const float s_T      = __ldg(params + 9);
    const float j0       = __ldg(params + 10);
    const float j_mu     = __ldg(params + 11);
    const float j_T      = __ldg(params + 12);
    const float v0       = __ldg(params + 13);
    const float v_mu     = __ldg(params + 14);
    const float mu0_base = __ldg(params + 15);
    const float mu0_T    = __ldg(params + 16);

    const float dT = __ldg(Tptr) - T_REF;

    Coef k;
    k.A = a0 + a_T * dT;  k.a_mu = a_mu;  k.a_mu2 = a_mu2;
    k.C = c0 + c_T * dT;  k.c_mu = c_mu;
    k.S = s0 + s_T * dT;  k.s_mu = s_mu;
    k.J = j0 + j_T * dT;  k.j_mu = j_mu;
    k.v0 = v0;            k.v_mu = v_mu;

    const float mu0 = fminf(fmaxf(mu0_base + mu0_T * dT, MU_MIN), MU_MAX);
    float mux = mu0, muy = mu0;

    const float2* __restrict__ up = (const float2*)u     + b;
    const float2* __restrict__ np = (const float2*)noise + b;

    const long long NB2 = (long long)N_CYCLES * HALF;     // float2 per plane
    float2* __restrict__ o0 = (float2*)out + b;           // mu
    float2* __restrict__ o1 = o0 + NB2;                   // component
    float2* __restrict__ o2 = o1 + NB2;                   // pi
    float2* __restrict__ o3 = o2 + NB2;                   // d1
    float2* __restrict__ o4 = o3 + NB2;                   // sigma1
    float2* __restrict__ o5 = o4 + NB2;                   // d2
    float2* __restrict__ o6 = o5 + NB2;                   // sigma2

    // software pipeline: prefetch depth 2
    float2 ub[2], nb[2];
    ub[0] = __ldcs(up);           nb[0] = __ldcs(np);
    ub[1] = __ldcs(up + HALF);    nb[1] = __ldcs(np + HALF);

    #pragma unroll 2
    for (int t = 0; t < N_CYCLES; ++t) {
        const float2 uc = ub[t & 1];
        const float2 nc = nb[t & 1];
        if (t + 2 < N_CYCLES) {
            const long long off = (long long)(t + 2) * HALF;
            ub[t & 1] = __ldcs(up + off);
            nb[t & 1] = __ldcs(np + off);
        }

        float pix, d1x, s1x, d2x, s2x, cx;
        float piy, d1y, s1y, d2y, s2y, cy;
        step_lane(k, mux, uc.x, nc.x, pix, d1x, s1x, d2x, s2x, cx);
        step_lane(k, muy, uc.y, nc.y, piy, d1y, s1y, d2y, s2y, cy);

        const long long idx = (long long)t * HALF;
        __stcs(o0 + idx, make_float2(mux, muy));
        __stcs(o1 + idx, make_float2(cx,  cy));
        __stcs(o2 + idx, make_float2(pix, piy));
        __stcs(o3 + idx, make_float2(d1x, d1y));
        __stcs(o4 + idx, make_float2(s1x, s1y));
        __stcs(o5 + idx, make_float2(d2x, d2y));
        __stcs(o6 + idx, make_float2(s2x, s2y));
    }
}

extern "C" void kernel_launch(void* const* d_in, const int* in_sizes, int n_in,
                              void* d_out, int out_size)
{
    const float* params = (const float*)d_in[0];
    const float* T      = (const float*)d_in[1];
    const float* u      = (const float*)d_in[2];
    const float* noise  = (const float*)d_in[3];
    float* out          = (float*)d_out;

    const int threads = 128;
    const int blocks  = HALF / threads;   // 32768 / 128 = 256 blocks
    galling_v6_kernel<<<blocks, threads>>>(params, T, u, noise, out);
}